// round 1
// baseline (speedup 1.0000x reference)
#include <cuda_runtime.h>
#include <cstdint>
#include <cstddef>

#define BATCH 4096
#define DA 768
#define DD 16384
#define KMAX 160

// ---------------- device scratch (static; no allocations) ----------------
__device__ float g_xc[BATCH * DA];                    // x - b_dec
__device__ float g_acts[(size_t)BATCH * DD];          // relu encoder output (256 MB)
__device__ float g_WdecT[(size_t)DD * DA];            // W_dec transposed (50 MB)
__device__ float g_kdot[BATCH];                       // fallback k-estimator dot
__device__ int   g_eq;                                // Wk1==W_enc && bk1==b_enc ?

// ---------------- small helpers (f32x2 packed math) ----------------
__device__ __forceinline__ unsigned long long pk2(float lo, float hi) {
    unsigned long long r;
    asm("mov.b64 %0, {%1, %2};" : "=l"(r) : "f"(lo), "f"(hi));
    return r;
}
__device__ __forceinline__ void upk2(unsigned long long v, float& lo, float& hi) {
    asm("mov.b64 {%0, %1}, %2;" : "=f"(lo), "=f"(hi) : "l"(v));
}
__device__ __forceinline__ void ffma2(unsigned long long& acc,
                                      unsigned long long a, unsigned long long b) {
    asm("fma.rn.f32x2 %0, %1, %2, %0;" : "+l"(acc) : "l"(a), "l"(b));
}

// ---------------- init: xc = x - b_dec ; zero kdot ; g_eq = 1 ----------------
__global__ void init_kernel(const float* __restrict__ x, const float* __restrict__ b_dec) {
    int i = blockIdx.x * 256 + threadIdx.x;
    if (i < BATCH * DA) g_xc[i] = x[i] - b_dec[i % DA];
    if (i < BATCH)      g_kdot[i] = 0.f;
    if (i == 0)         g_eq = 1;
}

// ---------------- equality check (is the k-estimator first layer == encoder?) ----------------
__global__ void eq_kernel(const float* __restrict__ We, const float* __restrict__ Wk1,
                          const float* __restrict__ be, const float* __restrict__ bk1) {
    int i = blockIdx.x * 256 + threadIdx.x;
    bool bad = false;
    if (i < DD * DA && We[i] != Wk1[i]) bad = true;
    if (i < DD && be[i] != bk1[i]) bad = true;
    if (bad) g_eq = 0;
}

// ---------------- transpose W_dec [DA][DD] -> g_WdecT [DD][DA] ----------------
__global__ void transpose_kernel(const float* __restrict__ Wdec) {
    __shared__ float t[32][33];
    int dd0 = blockIdx.x * 32, da0 = blockIdx.y * 32;
    int tx = threadIdx.x, ty = threadIdx.y;  // 32 x 8
#pragma unroll
    for (int j = 0; j < 4; j++)
        t[ty + j * 8][tx] = Wdec[(size_t)(da0 + ty + j * 8) * DD + dd0 + tx];
    __syncthreads();
#pragma unroll
    for (int j = 0; j < 4; j++)
        g_WdecT[(size_t)(dd0 + ty + j * 8) * DA + da0 + tx] = t[tx][ty + j * 8];
}

// ---------------- main GEMM: C[4096,16384] = relu(xc @ W^T + bias) ----------------
// store_acts=1 : write g_acts.  store_acts=0 : accumulate kdot += relu(.)*Wk2 (fallback path).
// exit_if_eq=1 : early-out when g_eq (the h-GEMM is redundant).
#define BKD 16
#define KTILES (DA / BKD)  // 48

__device__ __forceinline__ void stile(float (*S)[128], int qk, int qr, float4 v) {
    S[qk + 0][qr] = v.x; S[qk + 1][qr] = v.y; S[qk + 2][qr] = v.z; S[qk + 3][qr] = v.w;
}

__global__ void __launch_bounds__(256, 2) gemm_kernel(
    const float* __restrict__ Bw, const float* __restrict__ bias,
    const float* __restrict__ Wk2, int store_acts, int exit_if_eq)
{
    if (exit_if_eq && g_eq) return;

    __shared__ __align__(16) float As[2][BKD][128];
    __shared__ __align__(16) float Bs[2][BKD][128];

    int tid = threadIdx.x;
    int tx = tid & 15, ty = tid >> 4;
    int m0 = blockIdx.y * 128, n0 = blockIdx.x * 128;

    int qr0 = tid >> 2;                 // 0..63
    int qk0 = (tid & 3) * 4;            // 0,4,8,12
    int qr1 = qr0 + 64;

    const float* aP = g_xc + (size_t)(m0 + qr0) * DA + qk0;
    const float* bP = Bw   + (size_t)(n0 + qr0) * DA + qk0;
    const size_t rowoff = (size_t)64 * DA;

    unsigned long long acc[8][4];
#pragma unroll
    for (int i = 0; i < 8; i++)
#pragma unroll
        for (int j = 0; j < 4; j++) acc[i][j] = 0ull;

    float4 ra0 = *(const float4*)(aP);
    float4 ra1 = *(const float4*)(aP + rowoff);
    float4 rb0 = *(const float4*)(bP);
    float4 rb1 = *(const float4*)(bP + rowoff);
    stile(As[0], qk0, qr0, ra0); stile(As[0], qk0, qr1, ra1);
    stile(Bs[0], qk0, qr0, rb0); stile(Bs[0], qk0, qr1, rb1);
    __syncthreads();

    int buf = 0;
#pragma unroll 1
    for (int kt = 0; kt < KTILES; kt++) {
        if (kt + 1 < KTILES) {
            int off = (kt + 1) * BKD;
            ra0 = *(const float4*)(aP + off);
            ra1 = *(const float4*)(aP + off + rowoff);
            rb0 = *(const float4*)(bP + off);
            rb1 = *(const float4*)(bP + off + rowoff);
        }
#pragma unroll
        for (int k = 0; k < BKD; k++) {
            const float4* A4 = (const float4*)As[buf][k];
            const float4* B4 = (const float4*)Bs[buf][k];
            float4 a0 = A4[ty], a1 = A4[16 + ty];
            float4 b0 = B4[tx], b1 = B4[16 + tx];
            unsigned long long bb0 = pk2(b0.x, b0.y), bb1 = pk2(b0.z, b0.w);
            unsigned long long bb2 = pk2(b1.x, b1.y), bb3 = pk2(b1.z, b1.w);
            float av[8] = {a0.x, a0.y, a0.z, a0.w, a1.x, a1.y, a1.z, a1.w};
#pragma unroll
            for (int i = 0; i < 8; i++) {
                unsigned long long ad = pk2(av[i], av[i]);
                ffma2(acc[i][0], ad, bb0);
                ffma2(acc[i][1], ad, bb1);
                ffma2(acc[i][2], ad, bb2);
                ffma2(acc[i][3], ad, bb3);
            }
        }
        if (kt + 1 < KTILES) {
            int nb = buf ^ 1;
            stile(As[nb], qk0, qr0, ra0); stile(As[nb], qk0, qr1, ra1);
            stile(Bs[nb], qk0, qr0, rb0); stile(Bs[nb], qk0, qr1, rb1);
        }
        __syncthreads();
        buf ^= 1;
    }

    // -------- epilogue --------
    int cA = n0 + tx * 4, cB = n0 + 64 + tx * 4;
    float4 biA = *(const float4*)(bias + cA);
    float4 biB = *(const float4*)(bias + cB);

    if (store_acts) {
#pragma unroll
        for (int i = 0; i < 8; i++) {
            int row = m0 + ((i < 4) ? (ty * 4 + i) : (64 + ty * 4 + i - 4));
            float c0, c1, c2, c3, c4, c5, c6, c7;
            upk2(acc[i][0], c0, c1); upk2(acc[i][1], c2, c3);
            upk2(acc[i][2], c4, c5); upk2(acc[i][3], c6, c7);
            c0 = fmaxf(c0 + biA.x, 0.f); c1 = fmaxf(c1 + biA.y, 0.f);
            c2 = fmaxf(c2 + biA.z, 0.f); c3 = fmaxf(c3 + biA.w, 0.f);
            c4 = fmaxf(c4 + biB.x, 0.f); c5 = fmaxf(c5 + biB.y, 0.f);
            c6 = fmaxf(c6 + biB.z, 0.f); c7 = fmaxf(c7 + biB.w, 0.f);
            *(float4*)(g_acts + (size_t)row * DD + cA) = make_float4(c0, c1, c2, c3);
            *(float4*)(g_acts + (size_t)row * DD + cB) = make_float4(c4, c5, c6, c7);
        }
    } else {
        // fallback h-path: only the per-row dot with Wk2 is needed
        float4 wA = *(const float4*)(Wk2 + cA);
        float4 wB = *(const float4*)(Wk2 + cB);
        float* red = (float*)As;  // 128*16 floats, reuse (all compute done, synced)
#pragma unroll
        for (int i = 0; i < 8; i++) {
            int rl = (i < 4) ? (ty * 4 + i) : (64 + ty * 4 + i - 4);
            float c0, c1, c2, c3, c4, c5, c6, c7;
            upk2(acc[i][0], c0, c1); upk2(acc[i][1], c2, c3);
            upk2(acc[i][2], c4, c5); upk2(acc[i][3], c6, c7);
            c0 = fmaxf(c0 + biA.x, 0.f); c1 = fmaxf(c1 + biA.y, 0.f);
            c2 = fmaxf(c2 + biA.z, 0.f); c3 = fmaxf(c3 + biA.w, 0.f);
            c4 = fmaxf(c4 + biB.x, 0.f); c5 = fmaxf(c5 + biB.y, 0.f);
            c6 = fmaxf(c6 + biB.z, 0.f); c7 = fmaxf(c7 + biB.w, 0.f);
            float s = c0 * wA.x + c1 * wA.y + c2 * wA.z + c3 * wA.w
                    + c4 * wB.x + c5 * wB.y + c6 * wB.z + c7 * wB.w;
            red[rl * 16 + tx] = s;
        }
        __syncthreads();
        if (tid < 128) {
            float s = 0.f;
#pragma unroll
            for (int u = 0; u < 16; u++) s += red[tid * 16 + u];
            atomicAdd(&g_kdot[m0 + tid], s);
        }
    }
}

// ---------------- per-row: k-estimate + exact radix top-n select + sparse decode ----------------
__global__ void __launch_bounds__(256) select_decode_kernel(
    const float* __restrict__ Wk2, const float* __restrict__ bk2,
    const float* __restrict__ b_dec, const int* __restrict__ kptr,
    float* __restrict__ out)
{
    extern __shared__ __align__(16) float row[];  // DD floats
    __shared__ int   hist[256];
    __shared__ int   sredi[256];
    __shared__ float sredf[256];
    __shared__ int   scn[256];
    __shared__ int   scn1[256];
    __shared__ int   kept_idx[KMAX];
    __shared__ float kept_val[KMAX];
    __shared__ int   s_bucket, s_need;

    int b = blockIdx.x, tid = threadIdx.x;

    // load acts row into smem
    const float4* arow4 = (const float4*)(g_acts + (size_t)b * DD);
    float4* row4 = (float4*)row;
    for (int q = tid; q < DD / 4; q += 256) row4[q] = arow4[q];
    __syncthreads();

    // k-estimator pre-activation: deterministic block reduce
    int eq = g_eq;
    float local = 0.f;
    if (eq) {
        for (int j = tid; j < DD; j += 256) local += row[j] * Wk2[j];
    }
    sredf[tid] = local;
    __syncthreads();
    for (int s = 128; s > 0; s >>= 1) {
        if (tid < s) sredf[tid] += sredf[tid + s];
        __syncthreads();
    }
    float kd = eq ? sredf[0] : g_kdot[b];

    // parse k robustly (int32 / low word of int64 / float32)
    int iv = kptr[0];
    float kf = (iv > 0 && iv <= 1000000) ? (float)iv : __int_as_float(iv);
    float kest = 2.f * kf / (1.f + expf(-(kd + bk2[0])));
    int n = (int)floorf(kest);
    if ((float)n < kest) n++;
    if (n < 0) n = 0;
    if (n > DD) n = DD;

    // ---- exact MSB radix select of the n-th largest (positive floats only) ----
    unsigned v = 0;
    int need = n;
    bool vzero = false;  // threshold is 0 (keep all positives)
    if (n > 0) {
        for (int shift = 24; shift >= 0; shift -= 8) {
            hist[tid] = 0;
            __syncthreads();
            unsigned hi_mask = (shift == 24) ? 0u : (0xFFFFFFFFu << (shift + 8));
            for (int j = tid; j < DD; j += 256) {
                unsigned u = __float_as_uint(row[j]);
                bool want = (u != 0u) && ((u & hi_mask) == v);
                unsigned part = __ballot_sync(0xffffffffu, want);
                if (want) {
                    unsigned bk = (u >> shift) & 255u;
                    unsigned same = __match_any_sync(part, bk);
                    int leader = __ffs(same) - 1;
                    if ((int)(tid & 31) == leader) atomicAdd(&hist[bk], __popc(same));
                }
            }
            __syncthreads();
            // suffix-sum scan (descending buckets)
            int t = 255 - tid;
            int c = hist[t];
            sredi[tid] = c;
            __syncthreads();
            for (int off = 1; off < 256; off <<= 1) {
                int vv = (tid >= off) ? sredi[tid - off] : 0;
                __syncthreads();
                sredi[tid] += vv;
                __syncthreads();
            }
            int total = sredi[255];
            if (shift == 24 && total < need) { vzero = true; break; }  // fewer positives than n
            int above = sredi[tid] - c;
            if (c > 0 && above < need && need <= sredi[tid]) { s_bucket = t; s_need = need - above; }
            __syncthreads();
            v |= ((unsigned)s_bucket) << shift;
            need = s_need;
            __syncthreads();
        }
    }

    // ---- ordered (stable, deterministic) compaction of kept elements ----
    const int CH = DD / 256;  // 64 contiguous elements per thread
    int jbeg = tid * CH;
    int c0 = 0, c1 = 0;
    if (n > 0) {
        for (int j = jbeg; j < jbeg + CH; j++) {
            unsigned u = __float_as_uint(row[j]);
            if (u > v) c0++;
            else if (!vzero && u == v && u != 0u) c1++;
        }
    }
    scn[tid] = c0; scn1[tid] = c1;
    __syncthreads();
    for (int off = 1; off < 256; off <<= 1) {
        int a0 = (tid >= off) ? scn[tid - off] : 0;
        int a1 = (tid >= off) ? scn1[tid - off] : 0;
        __syncthreads();
        scn[tid] += a0; scn1[tid] += a1;
        __syncthreads();
    }
    int total0 = scn[255];
    int base0 = scn[tid] - c0;
    int base1 = scn1[tid] - c1;
    if (n > 0) {
        int w0 = base0, w1 = base1;
        for (int j = jbeg; j < jbeg + CH; j++) {
            unsigned u = __float_as_uint(row[j]);
            if (u > v) {
                if (w0 < KMAX) { kept_idx[w0] = j; kept_val[w0] = row[j]; }
                w0++;
            } else if (!vzero && u == v && u != 0u) {
                if (w1 < need) {
                    int slot = total0 + w1;
                    if (slot < KMAX) { kept_idx[slot] = j; kept_val[slot] = row[j]; }
                }
                w1++;
            }
        }
    }
    __syncthreads();
    int nk;
    if (n == 0) nk = 0;
    else if (vzero) nk = total0;
    else { int e = scn1[255]; nk = total0 + (need < e ? need : e); }
    if (nk > KMAX) nk = KMAX;

    // ---- sparse decode: out = b_dec + sum kept_val * WdecT[kept_idx] ----
    {
        int d = tid;  // DA = 3*256
        float a0 = b_dec[d], a1 = b_dec[d + 256], a2 = b_dec[d + 512];
        for (int t2 = 0; t2 < nk; t2++) {
            float vv = kept_val[t2];
            const float* wr = g_WdecT + (size_t)kept_idx[t2] * DA;
            a0 += vv * wr[d];
            a1 += vv * wr[d + 256];
            a2 += vv * wr[d + 512];
        }
        float* o = out + (size_t)b * DA;
        o[d] = a0; o[d + 256] = a1; o[d + 512] = a2;
    }
}

// ---------------- launch ----------------
extern "C" void kernel_launch(void* const* d_in, const int* in_sizes, int n_in,
                              void* d_out, int out_size) {
    const float* x    = (const float*)d_in[0];
    const float* Wenc = (const float*)d_in[1];
    const float* benc = (const float*)d_in[2];
    const float* Wdec = (const float*)d_in[3];
    const float* bdec = (const float*)d_in[4];
    const float* Wk1  = (const float*)d_in[5];
    const float* bk1  = (const float*)d_in[6];
    const float* Wk2  = (const float*)d_in[7];
    const float* bk2  = (const float*)d_in[8];
    const int*   kp   = (const int*)d_in[9];
    float* out = (float*)d_out;
    (void)in_sizes; (void)n_in; (void)out_size;

    init_kernel<<<(BATCH * DA + 255) / 256, 256>>>(x, bdec);
    eq_kernel<<<(DD * DA + 255) / 256, 256>>>(Wenc, Wk1, benc, bk1);
    transpose_kernel<<<dim3(DD / 32, DA / 32), dim3(32, 8)>>>(Wdec);

    dim3 g(DD / 128, BATCH / 128);
    gemm_kernel<<<g, 256>>>(Wenc, benc, Wk2, /*store_acts=*/1, /*exit_if_eq=*/0);
    gemm_kernel<<<g, 256>>>(Wk1, bk1, Wk2, /*store_acts=*/0, /*exit_if_eq=*/1);

    cudaFuncSetAttribute(select_decode_kernel,
                         cudaFuncAttributeMaxDynamicSharedMemorySize, DD * 4);
    select_decode_kernel<<<BATCH, 256, DD * 4>>>(Wk2, bk2, bdec, kp, out);
}